// round 1
// baseline (speedup 1.0000x reference)
#include <cuda_runtime.h>
#include <cuda_bf16.h>
#include <cstdint>

#define TT 512
#define CC 64
#define NB 1024  // B*T blocks

// scratch (allocation-free rule: __device__ globals)
__device__ float g_kp[NB * CC];
__device__ float g_qp[NB * CC];  // qp + b1 folded
__device__ float g_v [NB * CC];

// ---------------- kernel 1: projections ----------------
__global__ __launch_bounds__(64) void prep_kernel(
    const float* __restrict__ x, const float* __restrict__ pos,
    const float* __restrict__ W1, const float* __restrict__ b1,
    const float* __restrict__ Wv, const float* __restrict__ bv)
{
    const int bi = blockIdx.x;           // b*512 + t
    const int t  = bi & (TT - 1);
    const int c  = threadIdx.x;

    __shared__ float xs[CC], x1s[CC];
    float xv = x[bi * CC + c];
    xs[c]  = xv;
    x1s[c] = xv + pos[t * CC + c];
    __syncthreads();

    float ak = 0.f, aq = 0.f, av = 0.f;
#pragma unroll 16
    for (int k = 0; k < CC; k++) {
        float x1k = x1s[k];
        ak = fmaf(x1k, W1[k * CC + c], ak);
        aq = fmaf(x1k, W1[(CC + k) * CC + c], aq);
        av = fmaf(xs[k], Wv[k * CC + c], av);
    }
    g_kp[bi * CC + c] = ak;
    g_qp[bi * CC + c] = aq + b1[c];
    g_v [bi * CC + c] = av + bv[c];
}

// ---------------- kernel 2: fused attention row ----------------
// smem layout (bytes):
//   As      [128][136] bf16  : 34816   @ 0
//   Wt      [ 64][136] bf16  : 17408   @ 34816
//   qp_s    [64] f32         : 256     @ 52224
//   W2_s    [64] f32         : 256     @ 52480
//   logits  [512] f32        : 2048    @ 52736
//   red     [256] f32        : 1024    @ 54784
//   rbuf    [32] f32         : 128     @ 55808
#define SMEM_BYTES 55936

__global__ __launch_bounds__(256) void attn_kernel(
    const float* __restrict__ pdist,
    const float* __restrict__ W1,
    const float* __restrict__ W2,
    const float* __restrict__ b2,
    float* __restrict__ out)
{
    extern __shared__ char smem[];
    __nv_bfloat16* As = (__nv_bfloat16*)(smem);
    __nv_bfloat16* Wt = (__nv_bfloat16*)(smem + 34816);
    float* qp_s   = (float*)(smem + 52224);
    float* W2_s   = (float*)(smem + 52480);
    float* logits = (float*)(smem + 52736);
    float* red    = (float*)(smem + 54784);
    float* rbuf   = (float*)(smem + 55808);

    const int tid = threadIdx.x;
    const int bi  = blockIdx.x;
    const int b   = bi >> 9;
    const int i   = bi & (TT - 1);

    // W1p^T -> bf16 smem [n][k], padded stride 136 halves (conflict-free)
    for (int idx = tid; idx < 128 * 64; idx += 256) {
        int k = idx >> 6, n = idx & 63;
        Wt[n * 136 + k] = __float2bfloat16_rn(W1[(128 + k) * 64 + n]);
    }
    if (tid < 64) {
        qp_s[tid] = g_qp[bi * 64 + tid];
        W2_s[tid] = W2[tid];
    }
    __syncthreads();

    const int lane = tid & 31;
    const int w    = tid >> 5;
    const int g    = lane >> 2;
    const int tc   = lane & 3;

    const int nch = (i >> 7) + 1;  // causal: only chunks with jbase <= i

    uint32_t As_u   = (uint32_t)__cvta_generic_to_shared(As);
    uint32_t a_base = As_u + (uint32_t)((w * 16 + (lane & 7) + ((lane >> 3) & 1) * 8) * 272
                                        + (lane >> 4) * 16);

    for (int ch = 0; ch < nch; ch++) {
        const int jbase = ch << 7;
        // ---- load 128x128 fp32 chunk, convert to bf16, store padded ----
        const float4* src = (const float4*)(pdist + ((size_t)bi * TT + jbase) * 128);
#pragma unroll
        for (int it = 0; it < 16; it++) {
            int jloc = (tid >> 5) + it * 8;
            float4 vv = src[jloc * 32 + (tid & 31)];
            __nv_bfloat162 lo = __floats2bfloat162_rn(vv.x, vv.y);
            __nv_bfloat162 hi = __floats2bfloat162_rn(vv.z, vv.w);
            uint2 u;
            u.x = *(uint32_t*)&lo;
            u.y = *(uint32_t*)&hi;
            *(uint2*)((char*)As + jloc * 272 + (tid & 31) * 8) = u;
        }
        __syncthreads();

        // ---- mma: per warp 16 j-rows x 64 cols, K=128 ----
        float acc[32];
#pragma unroll
        for (int z = 0; z < 32; z++) acc[z] = 0.f;

#pragma unroll
        for (int kt = 0; kt < 8; kt++) {
            uint32_t a0, a1, a2, a3;
            asm volatile("ldmatrix.sync.aligned.m8n8.x4.shared.b16 {%0,%1,%2,%3}, [%4];"
                         : "=r"(a0), "=r"(a1), "=r"(a2), "=r"(a3)
                         : "r"(a_base + kt * 32));
#pragma unroll
            for (int nt = 0; nt < 8; nt++) {
                const uint32_t* wp =
                    (const uint32_t*)((char*)Wt + ((nt * 8 + g) * 136 + kt * 16 + 2 * tc) * 2);
                uint32_t b0 = wp[0];
                uint32_t b1r = wp[4];  // +8 halves
                asm volatile(
                    "mma.sync.aligned.m16n8k16.row.col.f32.bf16.bf16.f32 "
                    "{%0,%1,%2,%3}, {%4,%5,%6,%7}, {%8,%9}, {%0,%1,%2,%3};"
                    : "+f"(acc[nt * 4 + 0]), "+f"(acc[nt * 4 + 1]),
                      "+f"(acc[nt * 4 + 2]), "+f"(acc[nt * 4 + 3])
                    : "r"(a0), "r"(a1), "r"(a2), "r"(a3), "r"(b0), "r"(b1r));
            }
        }

        // ---- fused epilogue: +qp'+kp, exact gelu, dot W2 -> logits ----
        {
            const int j0 = jbase + w * 16 + g;
            const int j1 = j0 + 8;
            const float* kp0 = g_kp + ((size_t)b * TT + j0) * 64;
            const float* kp1 = kp0 + 8 * 64;
            float p0 = 0.f, p1 = 0.f;
#pragma unroll
            for (int nt = 0; nt < 8; nt++) {
                int c = nt * 8 + 2 * tc;
                float2 k0 = *(const float2*)(kp0 + c);
                float2 k1 = *(const float2*)(kp1 + c);
                float q0 = qp_s[c], q1 = qp_s[c + 1];
                float w20 = W2_s[c], w21 = W2_s[c + 1];
                float hh;
                hh = acc[nt * 4 + 0] + q0 + k0.x; p0 = fmaf(w20, hh * normcdff(hh), p0);
                hh = acc[nt * 4 + 1] + q1 + k0.y; p0 = fmaf(w21, hh * normcdff(hh), p0);
                hh = acc[nt * 4 + 2] + q0 + k1.x; p1 = fmaf(w20, hh * normcdff(hh), p1);
                hh = acc[nt * 4 + 3] + q1 + k1.y; p1 = fmaf(w21, hh * normcdff(hh), p1);
            }
            p0 += __shfl_xor_sync(0xffffffffu, p0, 1);
            p0 += __shfl_xor_sync(0xffffffffu, p0, 2);
            p1 += __shfl_xor_sync(0xffffffffu, p1, 1);
            p1 += __shfl_xor_sync(0xffffffffu, p1, 2);
            if (tc == 0) {
                logits[j0] = p0;
                logits[j1] = p1;
            }
        }
        __syncthreads();
    }

    // ---- causal softmax over j<=i (scaled logits) ----
    const float b2v = b2[0];
    float lmax = -1e30f;
    for (int j = tid; j <= i; j += 256) {
        float l = (logits[j] + b2v) * 0.125f;  // * C^-0.5
        logits[j] = l;
        lmax = fmaxf(lmax, l);
    }
#pragma unroll
    for (int o = 16; o; o >>= 1) lmax = fmaxf(lmax, __shfl_xor_sync(0xffffffffu, lmax, o));
    if (lane == 0) rbuf[w] = lmax;
    __syncthreads();
    float gmax = rbuf[0];
#pragma unroll
    for (int z = 1; z < 8; z++) gmax = fmaxf(gmax, rbuf[z]);
    __syncthreads();

    float lsum = 0.f;
    for (int j = tid; j <= i; j += 256) {
        float p = expf(logits[j] - gmax);
        logits[j] = p;
        lsum += p;
    }
#pragma unroll
    for (int o = 16; o; o >>= 1) lsum += __shfl_xor_sync(0xffffffffu, lsum, o);
    if (lane == 0) rbuf[w] = lsum;
    __syncthreads();
    float tot = rbuf[0];
#pragma unroll
    for (int z = 1; z < 8; z++) tot += rbuf[z];
    const float inv = 1.f / tot;
    __syncthreads();

    // ---- out[b,i,:] = (wei @ v) ----
    {
        const int h = tid & 63, q = tid >> 6;
        const float* vb = g_v + (size_t)b * TT * 64;
        float a0 = 0.f;
#pragma unroll 4
        for (int j = q; j <= i; j += 4)
            a0 = fmaf(logits[j], vb[j * 64 + h], a0);
        red[q * 64 + h] = a0;
        __syncthreads();
        if (tid < 64) {
            float r = red[tid] + red[tid + 64] + red[tid + 128] + red[tid + 192];
            out[bi * 64 + tid] = r * inv;
        }
    }
}

// ---------------- launcher ----------------
extern "C" void kernel_launch(void* const* d_in, const int* in_sizes, int n_in,
                              void* d_out, int out_size)
{
    const float* x     = (const float*)d_in[0];
    const float* pos   = (const float*)d_in[1];
    const float* pdist = (const float*)d_in[2];
    const float* W1    = (const float*)d_in[3];
    const float* b1    = (const float*)d_in[4];
    const float* W2    = (const float*)d_in[5];
    const float* b2    = (const float*)d_in[6];
    const float* Wv    = (const float*)d_in[7];
    const float* bv    = (const float*)d_in[8];
    float* out = (float*)d_out;

    cudaFuncSetAttribute(attn_kernel, cudaFuncAttributeMaxDynamicSharedMemorySize, SMEM_BYTES);

    prep_kernel<<<NB, 64>>>(x, pos, W1, b1, Wv, bv);
    attn_kernel<<<NB, 256, SMEM_BYTES>>>(pdist, W1, W2, b2, out);
}

// round 2
// speedup vs baseline: 1.0367x; 1.0367x over previous
#include <cuda_runtime.h>
#include <cuda_bf16.h>
#include <cstdint>

#define TT 512
#define CC 64
#define NB 1024  // B*T

// scratch (allocation-free rule: __device__ globals)
__device__ float g_kp[NB * CC];
__device__ float g_qp[NB * CC];  // qp + b1 folded
__device__ float g_v [NB * CC];
__device__ float g_logits[NB * TT];  // 2MB partial logits

// ---------------- kernel 1: projections ----------------
__global__ __launch_bounds__(64) void prep_kernel(
    const float* __restrict__ x, const float* __restrict__ pos,
    const float* __restrict__ W1, const float* __restrict__ b1,
    const float* __restrict__ Wv, const float* __restrict__ bv)
{
    const int bi = blockIdx.x;
    const int t  = bi & (TT - 1);
    const int c  = threadIdx.x;

    __shared__ float xs[CC], x1s[CC];
    float xv = x[bi * CC + c];
    xs[c]  = xv;
    x1s[c] = xv + pos[t * CC + c];
    __syncthreads();

    float ak = 0.f, aq = 0.f, av = 0.f;
#pragma unroll 16
    for (int k = 0; k < CC; k++) {
        float x1k = x1s[k];
        ak = fmaf(x1k, W1[k * CC + c], ak);
        aq = fmaf(x1k, W1[(CC + k) * CC + c], aq);
        av = fmaf(xs[k], Wv[k * CC + c], av);
    }
    g_kp[bi * CC + c] = ak;
    g_qp[bi * CC + c] = aq + b1[c];
    g_v [bi * CC + c] = av + bv[c];
}

// ---------------- kernel 2: one (b, i, chunk) per block ----------------
// smem layout (bytes):
//   As   [128][136] bf16 : 34816 @ 0
//   Wt   [ 64][136] bf16 : 17408 @ 34816
//   qp_s [64] f32        : 256   @ 52224
//   W2_s [64] f32        : 256   @ 52480
#define SMEM_BYTES 52736
#define NCHUNK_BLKS 1280  // sum over i of (i>>7)+1

__global__ __launch_bounds__(256) void attn_kernel(
    const float* __restrict__ pdist,
    const float* __restrict__ W1,
    const float* __restrict__ W2)
{
    extern __shared__ char smem[];
    __nv_bfloat16* As = (__nv_bfloat16*)(smem);
    __nv_bfloat16* Wt = (__nv_bfloat16*)(smem + 34816);
    float* qp_s = (float*)(smem + 52224);
    float* W2_s = (float*)(smem + 52480);

    const int tid = threadIdx.x;

    // decode (b, i, ch) from linear block id
    int z = blockIdx.x;
    int b = 0;
    if (z >= NCHUNK_BLKS) { b = 1; z -= NCHUNK_BLKS; }
    int ch, i;
    if (z < 512)       { ch = 0; i = z; }
    else if (z < 896)  { ch = 1; i = 128 + (z - 512); }
    else if (z < 1152) { ch = 2; i = 256 + (z - 896); }
    else               { ch = 3; i = 384 + (z - 1152); }
    const int bi    = b * TT + i;
    const int jbase = ch << 7;

    // ---- issue pdist chunk load first (long-latency LDGs front-batched) ----
    const float4* src = (const float4*)(pdist + ((size_t)bi * TT + jbase) * 128);
#pragma unroll
    for (int it = 0; it < 16; it++) {
        int jloc = (tid >> 5) + it * 8;
        float4 vv = src[jloc * 32 + (tid & 31)];
        __nv_bfloat162 lo = __floats2bfloat162_rn(vv.x, vv.y);
        __nv_bfloat162 hi = __floats2bfloat162_rn(vv.z, vv.w);
        uint2 u;
        u.x = *(uint32_t*)&lo;
        u.y = *(uint32_t*)&hi;
        *(uint2*)((char*)As + jloc * 272 + (tid & 31) * 8) = u;
    }

    // ---- W1p^T -> bf16 smem [n][k], padded stride 136 halves ----
    for (int idx = tid; idx < 128 * 64; idx += 256) {
        int k = idx >> 6, n = idx & 63;
        Wt[n * 136 + k] = __float2bfloat16_rn(W1[(128 + k) * 64 + n]);
    }
    if (tid < 64) {
        qp_s[tid] = g_qp[bi * 64 + tid];
        W2_s[tid] = W2[tid];
    }
    __syncthreads();

    const int lane = tid & 31;
    const int w    = tid >> 5;
    const int g    = lane >> 2;
    const int tc   = lane & 3;

    uint32_t As_u   = (uint32_t)__cvta_generic_to_shared(As);
    uint32_t a_base = As_u + (uint32_t)((w * 16 + (lane & 7) + ((lane >> 3) & 1) * 8) * 272
                                        + (lane >> 4) * 16);

    // ---- mma: per warp 16 j-rows x 64 cols, K=128 ----
    float acc[32];
#pragma unroll
    for (int zz = 0; zz < 32; zz++) acc[zz] = 0.f;

#pragma unroll
    for (int kt = 0; kt < 8; kt++) {
        uint32_t a0, a1, a2, a3;
        asm volatile("ldmatrix.sync.aligned.m8n8.x4.shared.b16 {%0,%1,%2,%3}, [%4];"
                     : "=r"(a0), "=r"(a1), "=r"(a2), "=r"(a3)
                     : "r"(a_base + kt * 32));
#pragma unroll
        for (int nt = 0; nt < 8; nt++) {
            const uint32_t* wp =
                (const uint32_t*)((char*)Wt + ((nt * 8 + g) * 136 + kt * 16 + 2 * tc) * 2);
            uint32_t b0 = wp[0];
            uint32_t b1r = wp[4];
            asm volatile(
                "mma.sync.aligned.m16n8k16.row.col.f32.bf16.bf16.f32 "
                "{%0,%1,%2,%3}, {%4,%5,%6,%7}, {%8,%9}, {%0,%1,%2,%3};"
                : "+f"(acc[nt * 4 + 0]), "+f"(acc[nt * 4 + 1]),
                  "+f"(acc[nt * 4 + 2]), "+f"(acc[nt * 4 + 3])
                : "r"(a0), "r"(a1), "r"(a2), "r"(a3), "r"(b0), "r"(b1r));
        }
    }

    // ---- fused epilogue: +qp'+kp, exact gelu, dot W2 -> partial logits ----
    {
        const int j0 = jbase + w * 16 + g;
        const int j1 = j0 + 8;
        const float* kp0 = g_kp + ((size_t)b * TT + j0) * 64;
        const float* kp1 = kp0 + 8 * 64;
        float p0 = 0.f, p1 = 0.f;
#pragma unroll
        for (int nt = 0; nt < 8; nt++) {
            int c = nt * 8 + 2 * tc;
            float2 k0 = *(const float2*)(kp0 + c);
            float2 k1 = *(const float2*)(kp1 + c);
            float q0 = qp_s[c], q1 = qp_s[c + 1];
            float w20 = W2_s[c], w21 = W2_s[c + 1];
            float hh;
            hh = acc[nt * 4 + 0] + q0 + k0.x; p0 = fmaf(w20, hh * normcdff(hh), p0);
            hh = acc[nt * 4 + 1] + q1 + k0.y; p0 = fmaf(w21, hh * normcdff(hh), p0);
            hh = acc[nt * 4 + 2] + q0 + k1.x; p1 = fmaf(w20, hh * normcdff(hh), p1);
            hh = acc[nt * 4 + 3] + q1 + k1.y; p1 = fmaf(w21, hh * normcdff(hh), p1);
        }
        p0 += __shfl_xor_sync(0xffffffffu, p0, 1);
        p0 += __shfl_xor_sync(0xffffffffu, p0, 2);
        p1 += __shfl_xor_sync(0xffffffffu, p1, 1);
        p1 += __shfl_xor_sync(0xffffffffu, p1, 2);
        if (tc == 0) {
            g_logits[bi * TT + j0] = p0;
            g_logits[bi * TT + j1] = p1;
        }
    }
}

// ---------------- kernel 3: causal softmax + wei@v ----------------
__global__ __launch_bounds__(256) void softmax_av_kernel(
    const float* __restrict__ b2, float* __restrict__ out)
{
    __shared__ float logits[TT];
    __shared__ float red[256];
    __shared__ float rbuf[8];

    const int tid = threadIdx.x;
    const int bi  = blockIdx.x;
    const int b   = bi >> 9;
    const int i   = bi & (TT - 1);
    const int lane = tid & 31;
    const int w    = tid >> 5;

    const float b2v = b2[0];
    float lmax = -1e30f;
    for (int j = tid; j <= i; j += 256) {
        float l = (g_logits[bi * TT + j] + b2v) * 0.125f;
        logits[j] = l;
        lmax = fmaxf(lmax, l);
    }
#pragma unroll
    for (int o = 16; o; o >>= 1) lmax = fmaxf(lmax, __shfl_xor_sync(0xffffffffu, lmax, o));
    if (lane == 0) rbuf[w] = lmax;
    __syncthreads();
    float gmax = rbuf[0];
#pragma unroll
    for (int zz = 1; zz < 8; zz++) gmax = fmaxf(gmax, rbuf[zz]);
    __syncthreads();

    float lsum = 0.f;
    for (int j = tid; j <= i; j += 256) {
        float p = expf(logits[j] - gmax);
        logits[j] = p;
        lsum += p;
    }
#pragma unroll
    for (int o = 16; o; o >>= 1) lsum += __shfl_xor_sync(0xffffffffu, lsum, o);
    if (lane == 0) rbuf[w] = lsum;
    __syncthreads();
    float tot = rbuf[0];
#pragma unroll
    for (int zz = 1; zz < 8; zz++) tot += rbuf[zz];
    const float inv = 1.f / tot;
    __syncthreads();

    const int h = tid & 63, q = tid >> 6;
    const float* vb = g_v + (size_t)b * TT * 64;
    float a0 = 0.f;
#pragma unroll 4
    for (int j = q; j <= i; j += 4)
        a0 = fmaf(logits[j], vb[j * 64 + h], a0);
    red[q * 64 + h] = a0;
    __syncthreads();
    if (tid < 64) {
        float r = red[tid] + red[tid + 64] + red[tid + 128] + red[tid + 192];
        out[bi * 64 + tid] = r * inv;
    }
}

// ---------------- launcher ----------------
extern "C" void kernel_launch(void* const* d_in, const int* in_sizes, int n_in,
                              void* d_out, int out_size)
{
    const float* x     = (const float*)d_in[0];
    const float* pos   = (const float*)d_in[1];
    const float* pdist = (const float*)d_in[2];
    const float* W1    = (const float*)d_in[3];
    const float* b1    = (const float*)d_in[4];
    const float* W2    = (const float*)d_in[5];
    const float* b2    = (const float*)d_in[6];
    const float* Wv    = (const float*)d_in[7];
    const float* bv    = (const float*)d_in[8];
    float* out = (float*)d_out;

    cudaFuncSetAttribute(attn_kernel, cudaFuncAttributeMaxDynamicSharedMemorySize, SMEM_BYTES);

    prep_kernel<<<NB, 64>>>(x, pos, W1, b1, Wv, bv);
    attn_kernel<<<2 * NCHUNK_BLKS, 256, SMEM_BYTES>>>(pdist, W1, W2);
    softmax_av_kernel<<<NB, 256>>>(b2, out);
}

// round 3
// speedup vs baseline: 1.5841x; 1.5280x over previous
#include <cuda_runtime.h>
#include <cuda_bf16.h>
#include <cstdint>

#define TT 512
#define CC 64
#define NB 1024  // B*T

// scratch (allocation-free rule: __device__ globals)
__device__ float g_kp[NB * CC];
__device__ float g_qp[NB * CC];        // qp + b1 folded
__device__ float g_v [NB * CC];
__device__ float g_logits[NB * TT];    // partial logits
__device__ __nv_bfloat16 g_Wt[64 * 128];  // W1p^T bf16, [n][k]

// ---------------- kernel 1: projections + W1p transpose ----------------
// blocks 0..127: 8 tokens each. blocks 128..135: fill g_Wt.
// dynamic smem floats: Wk@0 Wq@4096 Wv@8192 xs@12288 x1s@12800 (13312 f32)
#define PREP_SMEM (13312 * 4)

__global__ __launch_bounds__(256) void prep_kernel(
    const float* __restrict__ x, const float* __restrict__ pos,
    const float* __restrict__ W1, const float* __restrict__ b1,
    const float* __restrict__ Wv, const float* __restrict__ bv)
{
    const int tid = threadIdx.x;

    if (blockIdx.x >= 128) {
        // transpose W1p -> bf16 [n=64][k=128]
        int base = (blockIdx.x - 128) * 1024 + tid;  // 4 elems per thread
#pragma unroll
        for (int r = 0; r < 4; r++) {
            int idx = base + r * 256;       // 0..8191
            int n = idx >> 7, k = idx & 127;
            g_Wt[n * 128 + k] = __float2bfloat16_rn(W1[(128 + k) * 64 + n]);
        }
        return;
    }

    extern __shared__ float sm[];
    float* Wk  = sm;
    float* Wq  = sm + 4096;
    float* Wvs = sm + 8192;
    float* xs  = sm + 12288;   // [8][64]
    float* x1s = sm + 12800;   // [8][64]

    // coalesced weight staging: 12288 floats, 48/thread
#pragma unroll
    for (int r = 0; r < 16; r++) {
        int idx = tid + r * 256;           // 0..4095
        Wk [idx] = W1[idx];
        Wq [idx] = W1[4096 + idx];
        Wvs[idx] = Wv[idx];
    }
    // 8 tokens of x / x1
    const int t0 = blockIdx.x * 8;         // global token base (bi)
#pragma unroll
    for (int r = 0; r < 2; r++) {
        int idx = tid + r * 256;           // 0..511
        int tl = idx >> 6, c = idx & 63;
        float xv = x[(t0 + tl) * 64 + c];
        xs [idx] = xv;
        x1s[idx] = xv + pos[(((t0 + tl) & (TT - 1)) * 64) + c];
    }
    __syncthreads();

    const int ts = tid >> 6;   // 0..3
    const int c  = tid & 63;
#pragma unroll
    for (int p = 0; p < 2; p++) {
        const int tl = ts + 4 * p;
        const int bi = t0 + tl;
        float ak = 0.f, aq = 0.f, av = 0.f;
#pragma unroll 16
        for (int k = 0; k < 64; k++) {
            float x1v = x1s[tl * 64 + k];
            float xv  = xs [tl * 64 + k];
            ak = fmaf(x1v, Wk [k * 64 + c], ak);
            aq = fmaf(x1v, Wq [k * 64 + c], aq);
            av = fmaf(xv,  Wvs[k * 64 + c], av);
        }
        g_kp[bi * 64 + c] = ak;
        g_qp[bi * 64 + c] = aq + b1[c];
        g_v [bi * 64 + c] = av + bv[c];
    }
}

// ---------------- kernel 2: one (b, i, chunk) per block ----------------
// smem bytes: As[128][136]bf16 34816@0, Wt[64][136]bf16 17408@34816,
//             qp_s 256@52224, W2_s 256@52480
#define SMEM_BYTES 52736
#define NCHUNK_BLKS 1280

__global__ __launch_bounds__(256) void attn_kernel(
    const float* __restrict__ pdist,
    const float* __restrict__ W2)
{
    extern __shared__ char smem[];
    __nv_bfloat16* As = (__nv_bfloat16*)(smem);
    __nv_bfloat16* Wt = (__nv_bfloat16*)(smem + 34816);
    float* qp_s = (float*)(smem + 52224);
    float* W2_s = (float*)(smem + 52480);

    const int tid = threadIdx.x;

    // decode (b, i, ch)
    int z = blockIdx.x;
    int b = 0;
    if (z >= NCHUNK_BLKS) { b = 1; z -= NCHUNK_BLKS; }
    int ch, i;
    if (z < 512)       { ch = 0; i = z; }
    else if (z < 896)  { ch = 1; i = 128 + (z - 512); }
    else if (z < 1152) { ch = 2; i = 256 + (z - 896); }
    else               { ch = 3; i = 384 + (z - 1152); }
    const int bi    = b * TT + i;
    const int jbase = ch << 7;
    const int imax  = i - jbase;           // rows jloc > imax are masked

    // ---- pdist chunk load (fp32 -> bf16, padded), skip masked rows ----
    const float4* src = (const float4*)(pdist + ((size_t)bi * TT + jbase) * 128);
    {
        const int col  = tid & 31;
        const int rb   = tid >> 5;
#pragma unroll
        for (int it = 0; it < 16; it++) {
            int jloc = rb + it * 8;
            if (jloc <= imax) {
                float4 vv = src[jloc * 32 + col];
                __nv_bfloat162 lo = __floats2bfloat162_rn(vv.x, vv.y);
                __nv_bfloat162 hi = __floats2bfloat162_rn(vv.z, vv.w);
                uint2 u;
                u.x = *(uint32_t*)&lo;
                u.y = *(uint32_t*)&hi;
                *(uint2*)((char*)As + jloc * 272 + col * 8) = u;
            }
        }
    }

    // ---- Wt fill from precomputed g_Wt (coalesced 16B copies) ----
#pragma unroll
    for (int r = 0; r < 4; r++) {
        int s = tid + r * 256;             // 0..1023 segments
        int n = s >> 4, k8 = s & 15;
        uint4 u = *(const uint4*)((const char*)g_Wt + n * 256 + k8 * 16);
        *(uint4*)((char*)Wt + n * 272 + k8 * 16) = u;
    }
    if (tid < 64) {
        qp_s[tid] = g_qp[bi * 64 + tid];
        W2_s[tid] = W2[tid];
    }
    __syncthreads();

    const int lane = tid & 31;
    const int w    = tid >> 5;
    const int g    = lane >> 2;
    const int tc   = lane & 3;

    const int wrow = w * 16;               // warp's first row in chunk
    if (wrow > imax) return;               // whole warp masked (no later barriers)

    uint32_t As_u = (uint32_t)__cvta_generic_to_shared(As);
    uint32_t Wt_u = (uint32_t)__cvta_generic_to_shared(Wt);
    uint32_t a_base = As_u + (uint32_t)((wrow + (lane & 7) + ((lane >> 3) & 1) * 8) * 272
                                        + (lane >> 4) * 16);
    // B ldmatrix base: rows n within 16-row pair, k-half select
    const int nrow = (lane & 7) + ((lane >> 4) << 3);
    const int khalf = ((lane >> 3) & 1) * 8;
    uint32_t b_base = Wt_u + (uint32_t)((nrow * 136 + khalf) * 2);

    float acc[32];
#pragma unroll
    for (int zz = 0; zz < 32; zz++) acc[zz] = 0.f;

#pragma unroll
    for (int kt = 0; kt < 8; kt++) {
        uint32_t a0, a1, a2, a3;
        asm volatile("ldmatrix.sync.aligned.m8n8.x4.shared.b16 {%0,%1,%2,%3}, [%4];"
                     : "=r"(a0), "=r"(a1), "=r"(a2), "=r"(a3)
                     : "r"(a_base + kt * 32));
#pragma unroll
        for (int nt2 = 0; nt2 < 4; nt2++) {
            uint32_t r0, r1, r2, r3;
            asm volatile("ldmatrix.sync.aligned.m8n8.x4.shared.b16 {%0,%1,%2,%3}, [%4];"
                         : "=r"(r0), "=r"(r1), "=r"(r2), "=r"(r3)
                         : "r"(b_base + (uint32_t)(nt2 * 16 * 272 + kt * 32)));
            int nt = nt2 * 2;
            asm volatile(
                "mma.sync.aligned.m16n8k16.row.col.f32.bf16.bf16.f32 "
                "{%0,%1,%2,%3}, {%4,%5,%6,%7}, {%8,%9}, {%0,%1,%2,%3};"
                : "+f"(acc[nt * 4 + 0]), "+f"(acc[nt * 4 + 1]),
                  "+f"(acc[nt * 4 + 2]), "+f"(acc[nt * 4 + 3])
                : "r"(a0), "r"(a1), "r"(a2), "r"(a3), "r"(r0), "r"(r1));
            asm volatile(
                "mma.sync.aligned.m16n8k16.row.col.f32.bf16.bf16.f32 "
                "{%0,%1,%2,%3}, {%4,%5,%6,%7}, {%8,%9}, {%0,%1,%2,%3};"
                : "+f"(acc[nt * 4 + 4]), "+f"(acc[nt * 4 + 5]),
                  "+f"(acc[nt * 4 + 6]), "+f"(acc[nt * 4 + 7])
                : "r"(a0), "r"(a1), "r"(a2), "r"(a3), "r"(r2), "r"(r3));
        }
    }

    // ---- fused epilogue: +qp'+kp, exact gelu (erff), dot W2 ----
    {
        const int j0 = jbase + wrow + g;
        const int j1 = j0 + 8;
        const float* kp0 = g_kp + ((size_t)b * TT + j0) * 64;
        const float* kp1 = kp0 + 8 * 64;
        float p0 = 0.f, p1 = 0.f;
#pragma unroll
        for (int nt = 0; nt < 8; nt++) {
            int c = nt * 8 + 2 * tc;
            float2 k0 = *(const float2*)(kp0 + c);
            float2 k1 = *(const float2*)(kp1 + c);
            float q0 = qp_s[c], q1 = qp_s[c + 1];
            float w20 = W2_s[c], w21 = W2_s[c + 1];
            float hh, t, u;
            hh = acc[nt * 4 + 0] + q0 + k0.x;
            t = 0.5f * hh; u = erff(hh * 0.70710678118f);
            p0 = fmaf(w20, fmaf(t, u, t), p0);
            hh = acc[nt * 4 + 1] + q1 + k0.y;
            t = 0.5f * hh; u = erff(hh * 0.70710678118f);
            p0 = fmaf(w21, fmaf(t, u, t), p0);
            hh = acc[nt * 4 + 2] + q0 + k1.x;
            t = 0.5f * hh; u = erff(hh * 0.70710678118f);
            p1 = fmaf(w20, fmaf(t, u, t), p1);
            hh = acc[nt * 4 + 3] + q1 + k1.y;
            t = 0.5f * hh; u = erff(hh * 0.70710678118f);
            p1 = fmaf(w21, fmaf(t, u, t), p1);
        }
        p0 += __shfl_xor_sync(0xffffffffu, p0, 1);
        p0 += __shfl_xor_sync(0xffffffffu, p0, 2);
        p1 += __shfl_xor_sync(0xffffffffu, p1, 1);
        p1 += __shfl_xor_sync(0xffffffffu, p1, 2);
        if (tc == 0) {
            g_logits[bi * TT + j0] = p0;
            g_logits[bi * TT + j1] = p1;
        }
    }
}

// ---------------- kernel 3: causal softmax + wei@v ----------------
__global__ __launch_bounds__(256) void softmax_av_kernel(
    const float* __restrict__ b2, float* __restrict__ out)
{
    __shared__ float logits[TT];
    __shared__ float red[256];
    __shared__ float rbuf[8];

    const int tid = threadIdx.x;
    const int bi  = blockIdx.x;
    const int b   = bi >> 9;
    const int i   = bi & (TT - 1);
    const int lane = tid & 31;
    const int w    = tid >> 5;

    const float b2v = b2[0];
    float lmax = -1e30f;
    for (int j = tid; j <= i; j += 256) {
        float l = (g_logits[bi * TT + j] + b2v) * 0.125f;
        logits[j] = l;
        lmax = fmaxf(lmax, l);
    }
#pragma unroll
    for (int o = 16; o; o >>= 1) lmax = fmaxf(lmax, __shfl_xor_sync(0xffffffffu, lmax, o));
    if (lane == 0) rbuf[w] = lmax;
    __syncthreads();
    float gmax = rbuf[0];
#pragma unroll
    for (int zz = 1; zz < 8; zz++) gmax = fmaxf(gmax, rbuf[zz]);
    __syncthreads();

    float lsum = 0.f;
    for (int j = tid; j <= i; j += 256) {
        float p = expf(logits[j] - gmax);
        logits[j] = p;
        lsum += p;
    }
#pragma unroll
    for (int o = 16; o; o >>= 1) lsum += __shfl_xor_sync(0xffffffffu, lsum, o);
    if (lane == 0) rbuf[w] = lsum;
    __syncthreads();
    float tot = rbuf[0];
#pragma unroll
    for (int zz = 1; zz < 8; zz++) tot += rbuf[zz];
    const float inv = 1.f / tot;
    __syncthreads();

    const int h = tid & 63, q = tid >> 6;
    const float* vb = g_v + (size_t)b * TT * 64;
    float a0 = 0.f;
#pragma unroll 4
    for (int j = q; j <= i; j += 4)
        a0 = fmaf(logits[j], vb[j * 64 + h], a0);
    red[q * 64 + h] = a0;
    __syncthreads();
    if (tid < 64) {
        float r = red[tid] + red[tid + 64] + red[tid + 128] + red[tid + 192];
        out[bi * 64 + tid] = r * inv;
    }
}

// ---------------- launcher ----------------
extern "C" void kernel_launch(void* const* d_in, const int* in_sizes, int n_in,
                              void* d_out, int out_size)
{
    const float* x     = (const float*)d_in[0];
    const float* pos   = (const float*)d_in[1];
    const float* pdist = (const float*)d_in[2];
    const float* W1    = (const float*)d_in[3];
    const float* b1    = (const float*)d_in[4];
    const float* W2    = (const float*)d_in[5];
    const float* b2    = (const float*)d_in[6];
    const float* Wv    = (const float*)d_in[7];
    const float* bv    = (const float*)d_in[8];
    float* out = (float*)d_out;

    cudaFuncSetAttribute(prep_kernel, cudaFuncAttributeMaxDynamicSharedMemorySize, PREP_SMEM);
    cudaFuncSetAttribute(attn_kernel, cudaFuncAttributeMaxDynamicSharedMemorySize, SMEM_BYTES);

    prep_kernel<<<136, 256, PREP_SMEM>>>(x, pos, W1, b1, Wv, bv);
    attn_kernel<<<2 * NCHUNK_BLKS, 256, SMEM_BYTES>>>(pdist, W2);
    softmax_av_kernel<<<NB, 256>>>(b2, out);
}

// round 4
// speedup vs baseline: 1.5993x; 1.0096x over previous
#include <cuda_runtime.h>
#include <cuda_bf16.h>
#include <cstdint>

#define TT 512
#define CC 64
#define NB 1024  // B*T

// scratch (allocation-free rule: __device__ globals)
__device__ float g_kp[NB * CC];
__device__ float g_qp[NB * CC];        // qp + b1 folded
__device__ float g_v [NB * CC];
__device__ float g_logits[NB * TT];    // partial logits
__device__ __nv_bfloat16 g_Wt[64 * 128];  // W1p^T bf16, [n][k]

// ---------------- kernel 1: projections + W1p transpose ----------------
// blocks 0..255: 4 tokens each. blocks 256..263: fill g_Wt.
// smem floats: Wk@0 Wq@4096 Wv@8192 xs@12288 x1s@12544 (12800 f32)
#define PREP_SMEM (12800 * 4)

__global__ __launch_bounds__(256) void prep_kernel(
    const float* __restrict__ x, const float* __restrict__ pos,
    const float* __restrict__ W1, const float* __restrict__ b1,
    const float* __restrict__ Wv, const float* __restrict__ bv)
{
    const int tid = threadIdx.x;

    if (blockIdx.x >= 256) {
        // transpose W1p -> bf16 [n=64][k=128]
        int base = (blockIdx.x - 256) * 1024 + tid;
#pragma unroll
        for (int r = 0; r < 4; r++) {
            int idx = base + r * 256;       // 0..8191
            int n = idx >> 7, k = idx & 127;
            g_Wt[n * 128 + k] = __float2bfloat16_rn(W1[(128 + k) * 64 + n]);
        }
        return;
    }

    extern __shared__ float sm[];
    float4* sm4 = (float4*)sm;
    float* Wk  = sm;
    float* Wq  = sm + 4096;
    float* Wvs = sm + 8192;
    float* xs  = sm + 12288;   // [4][64]
    float* x1s = sm + 12544;   // [4][64]

    // float4 weight staging: 3072 float4, 12 per thread
    const float4* W1v = (const float4*)W1;
    const float4* Wvv = (const float4*)Wv;
#pragma unroll
    for (int r = 0; r < 4; r++) {
        int idx = tid + r * 256;           // 0..1023
        sm4[idx]        = W1v[idx];        // Wk
        sm4[1024 + idx] = W1v[1024 + idx]; // Wq
        sm4[2048 + idx] = Wvv[idx];        // Wv
    }
    // 4 tokens of x / x1 (one float per thread)
    const int t0 = blockIdx.x * 4;
    {
        int tl = tid >> 6, c = tid & 63;
        float xv = x[(t0 + tl) * 64 + c];
        xs [tid] = xv;
        x1s[tid] = xv + pos[(((t0 + tl) & (TT - 1)) * 64) + c];
    }
    __syncthreads();

    const int tl = tid >> 6;   // 0..3
    const int c  = tid & 63;
    const int bi = t0 + tl;
    float ak = 0.f, aq = 0.f, av = 0.f;
#pragma unroll 16
    for (int k = 0; k < 64; k++) {
        float x1v = x1s[tl * 64 + k];
        float xv  = xs [tl * 64 + k];
        ak = fmaf(x1v, Wk [k * 64 + c], ak);
        aq = fmaf(x1v, Wq [k * 64 + c], aq);
        av = fmaf(xv,  Wvs[k * 64 + c], av);
    }
    g_kp[bi * 64 + c] = ak;
    g_qp[bi * 64 + c] = aq + b1[c];
    g_v [bi * 64 + c] = av + bv[c];
}

// ---------------- kernel 2: one (b, i, chunk) per block ----------------
// smem bytes: As[128][136]bf16 34816@0, Wt[64][136]bf16 17408@34816,
//             qp_s 256@52224, W2_s 256@52480
#define SMEM_BYTES 52736
#define NCHUNK_BLKS 1280

__global__ __launch_bounds__(256) void attn_kernel(
    const float* __restrict__ pdist,
    const float* __restrict__ W2)
{
    extern __shared__ char smem[];
    __nv_bfloat16* As = (__nv_bfloat16*)(smem);
    __nv_bfloat16* Wt = (__nv_bfloat16*)(smem + 34816);
    float* qp_s = (float*)(smem + 52224);
    float* W2_s = (float*)(smem + 52480);

    const int tid = threadIdx.x;

    // decode (b, i, ch)
    int z = blockIdx.x;
    int b = 0;
    if (z >= NCHUNK_BLKS) { b = 1; z -= NCHUNK_BLKS; }
    int ch, i;
    if (z < 512)       { ch = 0; i = z; }
    else if (z < 896)  { ch = 1; i = 128 + (z - 512); }
    else if (z < 1152) { ch = 2; i = 256 + (z - 896); }
    else               { ch = 3; i = 384 + (z - 1152); }
    const int bi    = b * TT + i;
    const int jbase = ch << 7;
    const int imax  = i - jbase;           // rows jloc > imax are masked

    // ---- Wt fill from precomputed g_Wt (coalesced 16B copies) ----
#pragma unroll
    for (int r = 0; r < 4; r++) {
        int s = tid + r * 256;             // 0..1023 segments
        int n = s >> 4, k8 = s & 15;
        uint4 u = *(const uint4*)((const char*)g_Wt + n * 256 + k8 * 16);
        *(uint4*)((char*)Wt + n * 272 + k8 * 16) = u;
    }
    if (tid < 64) {
        qp_s[tid] = g_qp[bi * 64 + tid];
        W2_s[tid] = W2[tid];
    }
    __syncthreads();   // only barrier: Wt/qp_s ready

    const int lane = tid & 31;
    const int w    = tid >> 5;
    const int g    = lane >> 2;
    const int tc   = lane & 3;

    const int wrow = w * 16;               // warp's first row in chunk
    if (wrow > imax) return;               // whole warp masked
    const int rmaxi = imax - wrow;         // valid local rows: r <= rmaxi

    // ---- per-warp load of ITS OWN 16 rows (fp32 -> bf16, padded) ----
    const float4* src = (const float4*)(pdist + ((size_t)bi * TT + jbase) * 128);
#pragma unroll
    for (int r = 0; r < 16; r++) {
        if (r <= rmaxi) {
            int jloc = wrow + r;
            float4 vv = src[jloc * 32 + lane];
            __nv_bfloat162 lo = __floats2bfloat162_rn(vv.x, vv.y);
            __nv_bfloat162 hi = __floats2bfloat162_rn(vv.z, vv.w);
            uint2 u;
            u.x = *(uint32_t*)&lo;
            u.y = *(uint32_t*)&hi;
            *(uint2*)((char*)As + jloc * 272 + lane * 8) = u;
        }
    }
    __syncwarp();

    uint32_t As_u = (uint32_t)__cvta_generic_to_shared(As);
    uint32_t Wt_u = (uint32_t)__cvta_generic_to_shared(Wt);
    uint32_t a_base = As_u + (uint32_t)((wrow + (lane & 7) + ((lane >> 3) & 1) * 8) * 272
                                        + (lane >> 4) * 16);
    const int nrow  = (lane & 7) + ((lane >> 4) << 3);
    const int khalf = ((lane >> 3) & 1) * 8;
    uint32_t b_base = Wt_u + (uint32_t)((nrow * 136 + khalf) * 2);

    float acc[32];
#pragma unroll
    for (int zz = 0; zz < 32; zz++) acc[zz] = 0.f;

#pragma unroll
    for (int kt = 0; kt < 8; kt++) {
        uint32_t a0, a1, a2, a3;
        asm volatile("ldmatrix.sync.aligned.m8n8.x4.shared.b16 {%0,%1,%2,%3}, [%4];"
                     : "=r"(a0), "=r"(a1), "=r"(a2), "=r"(a3)
                     : "r"(a_base + kt * 32));
#pragma unroll
        for (int nt2 = 0; nt2 < 4; nt2++) {
            uint32_t r0, r1, r2, r3;
            asm volatile("ldmatrix.sync.aligned.m8n8.x4.shared.b16 {%0,%1,%2,%3}, [%4];"
                         : "=r"(r0), "=r"(r1), "=r"(r2), "=r"(r3)
                         : "r"(b_base + (uint32_t)(nt2 * 16 * 272 + kt * 32)));
            int nt = nt2 * 2;
            asm volatile(
                "mma.sync.aligned.m16n8k16.row.col.f32.bf16.bf16.f32 "
                "{%0,%1,%2,%3}, {%4,%5,%6,%7}, {%8,%9}, {%0,%1,%2,%3};"
                : "+f"(acc[nt * 4 + 0]), "+f"(acc[nt * 4 + 1]),
                  "+f"(acc[nt * 4 + 2]), "+f"(acc[nt * 4 + 3])
                : "r"(a0), "r"(a1), "r"(a2), "r"(a3), "r"(r0), "r"(r1));
            asm volatile(
                "mma.sync.aligned.m16n8k16.row.col.f32.bf16.bf16.f32 "
                "{%0,%1,%2,%3}, {%4,%5,%6,%7}, {%8,%9}, {%0,%1,%2,%3};"
                : "+f"(acc[nt * 4 + 4]), "+f"(acc[nt * 4 + 5]),
                  "+f"(acc[nt * 4 + 6]), "+f"(acc[nt * 4 + 7])
                : "r"(a0), "r"(a1), "r"(a2), "r"(a3), "r"(r2), "r"(r3));
        }
    }

    // ---- fused epilogue: +qp'+kp, exact gelu (erff), dot W2 ----
    {
        const int j0 = jbase + wrow + g;
        const int j1 = j0 + 8;
        const float* kp0 = g_kp + ((size_t)b * TT + j0) * 64;
        const float* kp1 = kp0 + 8 * 64;
        float p0 = 0.f, p1 = 0.f;
#pragma unroll
        for (int nt = 0; nt < 8; nt++) {
            int c = nt * 8 + 2 * tc;
            float2 k0 = *(const float2*)(kp0 + c);
            float2 k1 = *(const float2*)(kp1 + c);
            float q0 = qp_s[c], q1 = qp_s[c + 1];
            float w20 = W2_s[c], w21 = W2_s[c + 1];
            float hh, t, u;
            hh = acc[nt * 4 + 0] + q0 + k0.x;
            t = 0.5f * hh; u = erff(hh * 0.70710678118f);
            p0 = fmaf(w20, fmaf(t, u, t), p0);
            hh = acc[nt * 4 + 1] + q1 + k0.y;
            t = 0.5f * hh; u = erff(hh * 0.70710678118f);
            p0 = fmaf(w21, fmaf(t, u, t), p0);
            hh = acc[nt * 4 + 2] + q0 + k1.x;
            t = 0.5f * hh; u = erff(hh * 0.70710678118f);
            p1 = fmaf(w20, fmaf(t, u, t), p1);
            hh = acc[nt * 4 + 3] + q1 + k1.y;
            t = 0.5f * hh; u = erff(hh * 0.70710678118f);
            p1 = fmaf(w21, fmaf(t, u, t), p1);
        }
        p0 += __shfl_xor_sync(0xffffffffu, p0, 1);
        p0 += __shfl_xor_sync(0xffffffffu, p0, 2);
        p1 += __shfl_xor_sync(0xffffffffu, p1, 1);
        p1 += __shfl_xor_sync(0xffffffffu, p1, 2);
        if (tc == 0) {
            g_logits[bi * TT + j0] = p0;
            g_logits[bi * TT + j1] = p1;
        }
    }
}

// ---------------- kernel 3: causal softmax + wei@v ----------------
__global__ __launch_bounds__(256) void softmax_av_kernel(
    const float* __restrict__ b2, float* __restrict__ out)
{
    __shared__ float logits[TT];
    __shared__ float red[256];
    __shared__ float rbuf[8];

    const int tid = threadIdx.x;
    const int bi  = blockIdx.x;
    const int b   = bi >> 9;
    const int i   = bi & (TT - 1);
    const int lane = tid & 31;
    const int w    = tid >> 5;

    const float b2v = b2[0];
    float lmax = -1e30f;
    for (int j = tid; j <= i; j += 256) {
        float l = (g_logits[bi * TT + j] + b2v) * 0.125f;
        logits[j] = l;
        lmax = fmaxf(lmax, l);
    }
#pragma unroll
    for (int o = 16; o; o >>= 1) lmax = fmaxf(lmax, __shfl_xor_sync(0xffffffffu, lmax, o));
    if (lane == 0) rbuf[w] = lmax;
    __syncthreads();
    float gmax = rbuf[0];
#pragma unroll
    for (int zz = 1; zz < 8; zz++) gmax = fmaxf(gmax, rbuf[zz]);
    __syncthreads();

    float lsum = 0.f;
    for (int j = tid; j <= i; j += 256) {
        float p = expf(logits[j] - gmax);
        logits[j] = p;
        lsum += p;
    }
#pragma unroll
    for (int o = 16; o; o >>= 1) lsum += __shfl_xor_sync(0xffffffffu, lsum, o);
    if (lane == 0) rbuf[w] = lsum;
    __syncthreads();
    float tot = rbuf[0];
#pragma unroll
    for (int zz = 1; zz < 8; zz++) tot += rbuf[zz];
    const float inv = 1.f / tot;
    __syncthreads();

    const int h = tid & 63, q = tid >> 6;
    const float* vb = g_v + (size_t)b * TT * 64;
    float a0 = 0.f;
#pragma unroll 4
    for (int j = q; j <= i; j += 4)
        a0 = fmaf(logits[j], vb[j * 64 + h], a0);
    red[q * 64 + h] = a0;
    __syncthreads();
    if (tid < 64) {
        float r = red[tid] + red[tid + 64] + red[tid + 128] + red[tid + 192];
        out[bi * 64 + tid] = r * inv;
    }
}

// ---------------- launcher ----------------
extern "C" void kernel_launch(void* const* d_in, const int* in_sizes, int n_in,
                              void* d_out, int out_size)
{
    const float* x     = (const float*)d_in[0];
    const float* pos   = (const float*)d_in[1];
    const float* pdist = (const float*)d_in[2];
    const float* W1    = (const float*)d_in[3];
    const float* b1    = (const float*)d_in[4];
    const float* W2    = (const float*)d_in[5];
    const float* b2    = (const float*)d_in[6];
    const float* Wv    = (const float*)d_in[7];
    const float* bv    = (const float*)d_in[8];
    float* out = (float*)d_out;

    cudaFuncSetAttribute(prep_kernel, cudaFuncAttributeMaxDynamicSharedMemorySize, PREP_SMEM);
    cudaFuncSetAttribute(attn_kernel, cudaFuncAttributeMaxDynamicSharedMemorySize, SMEM_BYTES);

    prep_kernel<<<264, 256, PREP_SMEM>>>(x, pos, W1, b1, Wv, bv);
    attn_kernel<<<2 * NCHUNK_BLKS, 256, SMEM_BYTES>>>(pdist, W2);
    softmax_av_kernel<<<NB, 256>>>(b2, out);
}